// round 1
// baseline (speedup 1.0000x reference)
#include <cuda_runtime.h>
#include <stdint.h>

// TwoHotEmbedding: out[b,s,:] = W[i1[b,s]] + (i1!=i2 ? W[i2[b,s]] : 0)
// Shapes: i1,i2 [8,4096] int32; W [50257,512] f32; out [8,4096,512] f32.
//
// Pure memory-bound gather+add. One thread per float4 (16B) of output.
// Row = 512 floats = 128 float4. idx>>7 = token, idx&127 = chunk-in-row.

static constexpr int NTOK = 8 * 4096;       // 32768 tokens
static constexpr int CHUNKS = 512 / 4;      // 128 float4 per row
static constexpr long long TOTAL = (long long)NTOK * CHUNKS;  // 4,194,304

__global__ void __launch_bounds__(256)
twohot_kernel(const int* __restrict__ i1,
              const int* __restrict__ i2,
              const float4* __restrict__ W,
              float4* __restrict__ out)
{
    long long idx = (long long)blockIdx.x * blockDim.x + threadIdx.x;
    if (idx >= TOTAL) return;

    int t = (int)(idx >> 7);
    int c = (int)(idx & 127);

    int a = __ldg(i1 + t);
    int b = __ldg(i2 + t);

    float4 v = __ldg(W + (long long)a * CHUNKS + c);
    if (b != a) {
        float4 w = __ldg(W + (long long)b * CHUNKS + c);
        v.x += w.x; v.y += w.y; v.z += w.z; v.w += w.w;
    }
    out[idx] = v;
}

extern "C" void kernel_launch(void* const* d_in, const int* in_sizes, int n_in,
                              void* d_out, int out_size)
{
    const int*    i1 = (const int*)d_in[0];
    const int*    i2 = (const int*)d_in[1];
    const float4* W  = (const float4*)d_in[2];
    float4*       out = (float4*)d_out;

    const int threads = 256;
    const long long blocks = (TOTAL + threads - 1) / threads;  // 16384
    twohot_kernel<<<(unsigned)blocks, threads>>>(i1, i2, W, out);
}

// round 2
// speedup vs baseline: 1.2311x; 1.2311x over previous
#include <cuda_runtime.h>
#include <stdint.h>

// TwoHotEmbedding: out[b,s,:] = W[i1[b,s]] + (i1!=i2 ? W[i2[b,s]] : 0)
// i1,i2 [8,4096] int32; W [50257,512] f32; out [8,4096,512] f32.
//
// R2: warp-per-token. Each lane owns 4 float4 chunks of the 128-float4 row.
// Both gathers issued unconditionally (8 independent LDG.128 per thread,
// MLP=8) and blended with a warp-uniform 0/1 multiplier — no branch, no
// divergence, no load serialization. Output uses streaming stores (__stcs)
// so the 64MB output doesn't evict the weight rows from L2 (duplicate-token
// reuse is worth ~25MB of read traffic).

static constexpr int NTOK = 8 * 4096;   // 32768 tokens
static constexpr int CHUNKS = 128;      // float4 per row

__global__ void __launch_bounds__(256)
twohot_kernel(const int* __restrict__ i1,
              const int* __restrict__ i2,
              const float4* __restrict__ W,
              float4* __restrict__ out)
{
    int warp = blockIdx.x * (blockDim.x >> 5) + (threadIdx.x >> 5);
    int lane = threadIdx.x & 31;
    if (warp >= NTOK) return;

    int a = __ldg(i1 + warp);   // warp-uniform broadcast
    int b = __ldg(i2 + warp);

    const float4* ra = W + (long long)a * CHUNKS + lane;
    const float4* rb = W + (long long)b * CHUNKS + lane;
    float4* o = out + (long long)warp * CHUNKS + lane;

    // 8 independent loads, front-batched by ptxas.
    float4 a0 = __ldg(ra + 0);
    float4 a1 = __ldg(ra + 32);
    float4 a2 = __ldg(ra + 64);
    float4 a3 = __ldg(ra + 96);
    float4 b0 = __ldg(rb + 0);
    float4 b1 = __ldg(rb + 32);
    float4 b2 = __ldg(rb + 64);
    float4 b3 = __ldg(rb + 96);

    float m = (a != b) ? 1.0f : 0.0f;   // warp-uniform

    a0.x = fmaf(m, b0.x, a0.x); a0.y = fmaf(m, b0.y, a0.y);
    a0.z = fmaf(m, b0.z, a0.z); a0.w = fmaf(m, b0.w, a0.w);
    a1.x = fmaf(m, b1.x, a1.x); a1.y = fmaf(m, b1.y, a1.y);
    a1.z = fmaf(m, b1.z, a1.z); a1.w = fmaf(m, b1.w, a1.w);
    a2.x = fmaf(m, b2.x, a2.x); a2.y = fmaf(m, b2.y, a2.y);
    a2.z = fmaf(m, b2.z, a2.z); a2.w = fmaf(m, b2.w, a2.w);
    a3.x = fmaf(m, b3.x, a3.x); a3.y = fmaf(m, b3.y, a3.y);
    a3.z = fmaf(m, b3.z, a3.z); a3.w = fmaf(m, b3.w, a3.w);

    __stcs(o + 0,  a0);
    __stcs(o + 32, a1);
    __stcs(o + 64, a2);
    __stcs(o + 96, a3);
}

extern "C" void kernel_launch(void* const* d_in, const int* in_sizes, int n_in,
                              void* d_out, int out_size)
{
    const int*    i1 = (const int*)d_in[0];
    const int*    i2 = (const int*)d_in[1];
    const float4* W  = (const float4*)d_in[2];
    float4*       out = (float4*)d_out;

    const int threads = 256;                  // 8 warps = 8 tokens per block
    const int blocks = NTOK / 8;              // 4096 blocks
    twohot_kernel<<<blocks, threads>>>(i1, i2, W, out);
}

// round 4
// speedup vs baseline: 1.2326x; 1.0013x over previous
#include <cuda_runtime.h>
#include <stdint.h>

// TwoHotEmbedding: out[b,s,:] = W[i1[b,s]] + (i1!=i2 ? W[i2[b,s]] : 0)
// i1,i2 [8,4096] int32; W [50257,512] f32; out [8,4096,512] f32.
//
// R4: same warp-per-token / MLP=8 structure as R2. W gathers carry an
// L2::evict_last cache policy (createpolicy + ld.global.nc.L2::cache_hint —
// the inline .L2::evict_last modifier is v8.b32-only on sm_103) so the 98MB
// weight table wins L2 residency against the 64MB output, which is stored
// with .cs (evict_first). R2 evidence: the 37MB of read DRAM traffic was
// L2 churn across graph replays; pinning W should mostly eliminate it.

static constexpr int NTOK = 8 * 4096;   // 32768 tokens
static constexpr int CHUNKS = 128;      // float4 per row

__device__ __forceinline__ float4 ldg_pol(const float4* p, uint64_t pol)
{
    float4 v;
    asm volatile("ld.global.nc.L2::cache_hint.v4.f32 {%0,%1,%2,%3}, [%4], %5;"
                 : "=f"(v.x), "=f"(v.y), "=f"(v.z), "=f"(v.w)
                 : "l"(p), "l"(pol));
    return v;
}

__global__ void __launch_bounds__(256)
twohot_kernel(const int* __restrict__ i1,
              const int* __restrict__ i2,
              const float4* __restrict__ W,
              float4* __restrict__ out)
{
    int warp = blockIdx.x * (blockDim.x >> 5) + (threadIdx.x >> 5);
    int lane = threadIdx.x & 31;
    if (warp >= NTOK) return;

    uint64_t pol;
    asm("createpolicy.fractional.L2::evict_last.b64 %0, 1.0;" : "=l"(pol));

    int a = __ldg(i1 + warp);   // warp-uniform broadcast
    int b = __ldg(i2 + warp);

    const float4* ra = W + (long long)a * CHUNKS + lane;
    const float4* rb = W + (long long)b * CHUNKS + lane;
    float4* o = out + (long long)warp * CHUNKS + lane;

    // 8 independent loads in flight, all L2-evict-last.
    float4 a0 = ldg_pol(ra + 0,  pol);
    float4 a1 = ldg_pol(ra + 32, pol);
    float4 a2 = ldg_pol(ra + 64, pol);
    float4 a3 = ldg_pol(ra + 96, pol);
    float4 b0 = ldg_pol(rb + 0,  pol);
    float4 b1 = ldg_pol(rb + 32, pol);
    float4 b2 = ldg_pol(rb + 64, pol);
    float4 b3 = ldg_pol(rb + 96, pol);

    float m = (a != b) ? 1.0f : 0.0f;   // warp-uniform

    a0.x = fmaf(m, b0.x, a0.x); a0.y = fmaf(m, b0.y, a0.y);
    a0.z = fmaf(m, b0.z, a0.z); a0.w = fmaf(m, b0.w, a0.w);
    a1.x = fmaf(m, b1.x, a1.x); a1.y = fmaf(m, b1.y, a1.y);
    a1.z = fmaf(m, b1.z, a1.z); a1.w = fmaf(m, b1.w, a1.w);
    a2.x = fmaf(m, b2.x, a2.x); a2.y = fmaf(m, b2.y, a2.y);
    a2.z = fmaf(m, b2.z, a2.z); a2.w = fmaf(m, b2.w, a2.w);
    a3.x = fmaf(m, b3.x, a3.x); a3.y = fmaf(m, b3.y, a3.y);
    a3.z = fmaf(m, b3.z, a3.z); a3.w = fmaf(m, b3.w, a3.w);

    __stcs(o + 0,  a0);
    __stcs(o + 32, a1);
    __stcs(o + 64, a2);
    __stcs(o + 96, a3);
}

extern "C" void kernel_launch(void* const* d_in, const int* in_sizes, int n_in,
                              void* d_out, int out_size)
{
    const int*    i1 = (const int*)d_in[0];
    const int*    i2 = (const int*)d_in[1];
    const float4* W  = (const float4*)d_in[2];
    float4*       out = (float4*)d_out;

    const int threads = 256;                  // 8 warps = 8 tokens per block
    const int blocks = NTOK / 8;              // 4096 blocks
    twohot_kernel<<<blocks, threads>>>(i1, i2, W, out);
}